// round 3
// baseline (speedup 1.0000x reference)
#include <cuda_runtime.h>

// Dense3DSpatialTransformer: trilinear warp of a (1,1,160,192,224) volume by a
// (1,3,160,192,224) displacement field. Output (1,1,160,192,224) fp32.
//
// Reference pads input1 by 1 (zeros) on each spatial side, then samples at
// (disp + mesh + 1) in padded coords with floor/floor+1 trilinear corners,
// indices clipped into the padded volume. Clipping only ever redirects an
// index onto the zero padding ring (or further clamping of an already-zero
// sample), so we can skip the pad entirely: bounds-checked sampler returning
// 0 outside padded-interior [1,D]x[1,H]x[1,W], unclipped weights.

namespace {
constexpr int D = 160, H = 192, W = 224;
constexpr int HW  = H * W;          // 43008
constexpr int VOL = D * H * W;      // 6881280
}

// Sample one (d,h) row at padded w-index iw; rowok = (d,h) in bounds.
__device__ __forceinline__ float samp_row(const float* __restrict__ row,
                                          bool rowok, int iw) {
    unsigned uw = (unsigned)(iw - 1);
    if (rowok && uw < (unsigned)W) {
        return __ldg(row + uw);
    }
    return 0.0f;
}

__device__ __forceinline__ float sel4(const float4 v, int k) {
    switch (k) {
        case 0: return v.x;
        case 1: return v.y;
        case 2: return v.z;
        default: return v.w;
    }
}

__global__ void __launch_bounds__(256)
warp3d_kernel(const float* __restrict__ img,    // VOL floats
              const float* __restrict__ disp,   // 3*VOL floats (dD, dH, dW)
              float* __restrict__ out)          // VOL floats
{
    int t = blockIdx.x * blockDim.x + threadIdx.x;
    constexpr int N4 = VOL / 4;
    if (t >= N4) return;
    int n = t * 4;

    int w0 = n % W;
    int h  = (n / W) % H;
    int d  = n / HW;

    float4 dd = *reinterpret_cast<const float4*>(disp + n);
    float4 dh = *reinterpret_cast<const float4*>(disp + VOL + n);
    float4 dw = *reinterpret_cast<const float4*>(disp + 2 * VOL + n);

    float resv[4];

    #pragma unroll
    for (int k = 0; k < 4; k++) {
        float Dup = sel4(dd, k) + (float)d + 1.0f;
        float Hup = sel4(dh, k) + (float)h + 1.0f;
        float Wup = sel4(dw, k) + (float)(w0 + k) + 1.0f;

        float fd = floorf(Dup);
        float fh = floorf(Hup);
        float fw = floorf(Wup);
        int df = (int)fd, hf = (int)fh, wf = (int)fw;
        int dc = df + 1,  hc = hf + 1,  wc = wf + 1;

        // weight for the floor corner (reference: wd = ceil - up)
        float wd = (fd + 1.0f) - Dup;
        float wh = (fh + 1.0f) - Hup;
        float ww = (fw + 1.0f) - Wup;
        float wd1 = 1.0f - wd;
        float wh1 = 1.0f - wh;
        float ww1 = 1.0f - ww;

        // Row validity in unpadded coords (padded interior is [1..D]x[1..H]).
        bool dfo = (unsigned)(df - 1) < (unsigned)D;
        bool dco = (unsigned)(dc - 1) < (unsigned)D;
        bool hfo = (unsigned)(hf - 1) < (unsigned)H;
        bool hco = (unsigned)(hc - 1) < (unsigned)H;

        const float* row_ff = img + (ptrdiff_t)(df - 1) * HW + (ptrdiff_t)(hf - 1) * W;
        const float* row_fc = row_ff + W;        // hc = hf + 1
        const float* row_cf = row_ff + HW;       // dc = df + 1
        const float* row_cc = row_cf + W;

        // Reference summation order: d in (f,c), h in (f,c), w in (f,c)
        float acc;
        acc  = samp_row(row_ff, dfo && hfo, wf) * (wd  * wh  * ww );
        acc += samp_row(row_ff, dfo && hfo, wc) * (wd  * wh  * ww1);
        acc += samp_row(row_fc, dfo && hco, wf) * (wd  * wh1 * ww );
        acc += samp_row(row_fc, dfo && hco, wc) * (wd  * wh1 * ww1);
        acc += samp_row(row_cf, dco && hfo, wf) * (wd1 * wh  * ww );
        acc += samp_row(row_cf, dco && hfo, wc) * (wd1 * wh  * ww1);
        acc += samp_row(row_cc, dco && hco, wf) * (wd1 * wh1 * ww );
        acc += samp_row(row_cc, dco && hco, wc) * (wd1 * wh1 * ww1);

        resv[k] = acc;
    }

    float4 res = make_float4(resv[0], resv[1], resv[2], resv[3]);
    *reinterpret_cast<float4*>(out + n) = res;
}

extern "C" void kernel_launch(void* const* d_in, const int* in_sizes, int n_in,
                              void* d_out, int out_size) {
    const float* img  = (const float*)d_in[0];   // input1: VOL elements
    const float* disp = (const float*)d_in[1];   // input2: 3*VOL elements
    float* out = (float*)d_out;

    constexpr int N4 = VOL / 4;
    constexpr int TPB = 256;
    int blocks = (N4 + TPB - 1) / TPB;
    warp3d_kernel<<<blocks, TPB>>>(img, disp, out);
}

// round 4
// speedup vs baseline: 1.0322x; 1.0322x over previous
#include <cuda_runtime.h>

// Dense3DSpatialTransformer: trilinear warp of a (1,1,160,192,224) volume by a
// (1,3,160,192,224) displacement field. Output (1,1,160,192,224) fp32.
//
// Reference pads input1 by 1 (zeros) on each side and samples at
// (disp + mesh + 1) in padded coords with floor/floor+1 trilinear corners,
// indices clipped into the padded volume. Clipping only ever lands clipped
// samples on the zero pad ring, so: bounds-checked sampler returning 0
// outside padded-interior [1,D]x[1,H]x[1,W], unclipped weights.
//
// R3 -> R4: ncu showed L1tex-bound (L1 70.8%, DRAM 23%). Switched from
// 4 voxels/thread to 1 voxel/thread so each gather LDG spans ~128B across
// the warp instead of ~512B, cutting L1 wavefronts per gather ~2.5x.

namespace {
constexpr int D = 160, H = 192, W = 224;
constexpr int HW  = H * W;          // 43008
constexpr int VOL = D * H * W;      // 6881280
}

// Sample one (d,h) row at padded w-index iw; rowok = (d,h) row in bounds.
__device__ __forceinline__ float samp_row(const float* __restrict__ row,
                                          bool rowok, int iw) {
    unsigned uw = (unsigned)(iw - 1);
    if (rowok && uw < (unsigned)W) {
        return __ldg(row + uw);
    }
    return 0.0f;
}

__global__ void __launch_bounds__(256)
warp3d_kernel(const float* __restrict__ img,    // VOL floats
              const float* __restrict__ disp,   // 3*VOL floats (dD, dH, dW)
              float* __restrict__ out)          // VOL floats
{
    int n = blockIdx.x * blockDim.x + threadIdx.x;
    if (n >= VOL) return;

    int w = n % W;
    int h = (n / W) % H;
    int d = n / HW;

    float ddv = __ldg(disp + n);
    float dhv = __ldg(disp + VOL + n);
    float dwv = __ldg(disp + 2 * VOL + n);

    float Dup = ddv + (float)d + 1.0f;
    float Hup = dhv + (float)h + 1.0f;
    float Wup = dwv + (float)w + 1.0f;

    float fd = floorf(Dup);
    float fh = floorf(Hup);
    float fw = floorf(Wup);
    int df = (int)fd, hf = (int)fh, wf = (int)fw;
    int dc = df + 1,  hc = hf + 1,  wc = wf + 1;

    // Weight for the floor corner (reference: wd = ceil - up).
    float wd = (fd + 1.0f) - Dup;
    float wh = (fh + 1.0f) - Hup;
    float ww = (fw + 1.0f) - Wup;
    float wd1 = 1.0f - wd;
    float wh1 = 1.0f - wh;
    float ww1 = 1.0f - ww;

    // Row validity in unpadded coords (padded interior is [1..D]x[1..H]).
    bool dfo = (unsigned)(df - 1) < (unsigned)D;
    bool dco = (unsigned)(dc - 1) < (unsigned)D;
    bool hfo = (unsigned)(hf - 1) < (unsigned)H;
    bool hco = (unsigned)(hc - 1) < (unsigned)H;

    const float* row_ff = img + (ptrdiff_t)(df - 1) * HW + (ptrdiff_t)(hf - 1) * W;
    const float* row_fc = row_ff + W;        // hc = hf + 1
    const float* row_cf = row_ff + HW;       // dc = df + 1
    const float* row_cc = row_cf + W;

    // Reference summation order: d in (f,c), h in (f,c), w in (f,c).
    float acc;
    acc  = samp_row(row_ff, dfo && hfo, wf) * (wd  * wh  * ww );
    acc += samp_row(row_ff, dfo && hfo, wc) * (wd  * wh  * ww1);
    acc += samp_row(row_fc, dfo && hco, wf) * (wd  * wh1 * ww );
    acc += samp_row(row_fc, dfo && hco, wc) * (wd  * wh1 * ww1);
    acc += samp_row(row_cf, dco && hfo, wf) * (wd1 * wh  * ww );
    acc += samp_row(row_cf, dco && hfo, wc) * (wd1 * wh  * ww1);
    acc += samp_row(row_cc, dco && hco, wf) * (wd1 * wh1 * ww );
    acc += samp_row(row_cc, dco && hco, wc) * (wd1 * wh1 * ww1);

    out[n] = acc;
}

extern "C" void kernel_launch(void* const* d_in, const int* in_sizes, int n_in,
                              void* d_out, int out_size) {
    const float* img  = (const float*)d_in[0];   // input1: VOL elements
    const float* disp = (const float*)d_in[1];   // input2: 3*VOL elements
    float* out = (float*)d_out;

    constexpr int TPB = 256;
    int blocks = (VOL + TPB - 1) / TPB;
    warp3d_kernel<<<blocks, TPB>>>(img, disp, out);
}

// round 5
// speedup vs baseline: 1.1032x; 1.0688x over previous
#include <cuda_runtime.h>

// Dense3DSpatialTransformer: trilinear warp of a (1,1,160,192,224) volume by a
// (1,3,160,192,224) displacement field. Output (1,1,160,192,224) fp32.
//
// Reference pads input1 by 1 (zeros) on each side and samples at
// (disp + mesh + 1) in padded coords with floor/floor+1 trilinear corners,
// indices clipped into the padded volume. Clipping only ever lands clipped
// samples on the zero pad ring, so: bounds-checked sampler returning 0
// outside padded-interior [1,D]x[1,H]x[1,W], unclipped weights.
//
// R4 -> R5: L1=81%, L2=50%, DRAM=24%, issue=39% at 63.6us. 1D blocks have no
// h/d reuse inside a block, so neighboring blocks on other SMs re-pull the
// same image lines through L2. Switch to 2D tiles (32 wide x 8 high, fixed d)
// so the ~2x2x(20 rows) gather footprint is reused by all 256 voxels of the
// block, cutting L2 traffic and raising L1 hit rate (less exposed latency).

namespace {
constexpr int D = 160, H = 192, W = 224;
constexpr int HW  = H * W;          // 43008
constexpr int VOL = D * H * W;      // 6881280
}

// Sample one (d,h) row at padded w-index iw; rowok = (d,h) row in bounds.
__device__ __forceinline__ float samp_row(const float* __restrict__ row,
                                          bool rowok, int iw) {
    unsigned uw = (unsigned)(iw - 1);
    if (rowok && uw < (unsigned)W) {
        return __ldg(row + uw);
    }
    return 0.0f;
}

__global__ void __launch_bounds__(256)
warp3d_kernel(const float* __restrict__ img,    // VOL floats
              const float* __restrict__ disp,   // 3*VOL floats (dD, dH, dW)
              float* __restrict__ out)          // VOL floats
{
    // Block covers a 32(w) x 8(h) tile of one d-slice.
    int w = blockIdx.x * 32 + threadIdx.x;
    int h = blockIdx.y * 8 + threadIdx.y;
    int d = blockIdx.z;
    int n = d * HW + h * W + w;

    float ddv = __ldg(disp + n);
    float dhv = __ldg(disp + VOL + n);
    float dwv = __ldg(disp + 2 * VOL + n);

    float Dup = ddv + (float)d + 1.0f;
    float Hup = dhv + (float)h + 1.0f;
    float Wup = dwv + (float)w + 1.0f;

    float fd = floorf(Dup);
    float fh = floorf(Hup);
    float fw = floorf(Wup);
    int df = (int)fd, hf = (int)fh, wf = (int)fw;
    int dc = df + 1,  hc = hf + 1,  wc = wf + 1;

    // Weight for the floor corner (reference: wd = ceil - up).
    float wd = (fd + 1.0f) - Dup;
    float wh = (fh + 1.0f) - Hup;
    float ww = (fw + 1.0f) - Wup;
    float wd1 = 1.0f - wd;
    float wh1 = 1.0f - wh;
    float ww1 = 1.0f - ww;

    // Row validity in unpadded coords (padded interior is [1..D]x[1..H]).
    bool dfo = (unsigned)(df - 1) < (unsigned)D;
    bool dco = (unsigned)(dc - 1) < (unsigned)D;
    bool hfo = (unsigned)(hf - 1) < (unsigned)H;
    bool hco = (unsigned)(hc - 1) < (unsigned)H;

    const float* row_ff = img + (ptrdiff_t)(df - 1) * HW + (ptrdiff_t)(hf - 1) * W;
    const float* row_fc = row_ff + W;        // hc = hf + 1
    const float* row_cf = row_ff + HW;       // dc = df + 1
    const float* row_cc = row_cf + W;

    // Reference summation order: d in (f,c), h in (f,c), w in (f,c).
    float acc;
    acc  = samp_row(row_ff, dfo && hfo, wf) * (wd  * wh  * ww );
    acc += samp_row(row_ff, dfo && hfo, wc) * (wd  * wh  * ww1);
    acc += samp_row(row_fc, dfo && hco, wf) * (wd  * wh1 * ww );
    acc += samp_row(row_fc, dfo && hco, wc) * (wd  * wh1 * ww1);
    acc += samp_row(row_cf, dco && hfo, wf) * (wd1 * wh  * ww );
    acc += samp_row(row_cf, dco && hfo, wc) * (wd1 * wh  * ww1);
    acc += samp_row(row_cc, dco && hco, wf) * (wd1 * wh1 * ww );
    acc += samp_row(row_cc, dco && hco, wc) * (wd1 * wh1 * ww1);

    out[n] = acc;
}

extern "C" void kernel_launch(void* const* d_in, const int* in_sizes, int n_in,
                              void* d_out, int out_size) {
    const float* img  = (const float*)d_in[0];   // input1: VOL elements
    const float* disp = (const float*)d_in[1];   // input2: 3*VOL elements
    float* out = (float*)d_out;

    dim3 block(32, 8, 1);
    dim3 grid(W / 32, H / 8, D);   // 7 x 24 x 160
    warp3d_kernel<<<grid, block>>>(img, disp, out);
}

// round 6
// speedup vs baseline: 1.2817x; 1.1618x over previous
#include <cuda_runtime.h>

// Dense3DSpatialTransformer: trilinear warp of a (1,1,160,192,224) volume by a
// (1,3,160,192,224) displacement field. Output (1,1,160,192,224) fp32.
//
// Reference pads input1 by 1 (zeros) per side, samples at (disp + mesh + 1)
// in padded coords with floor/floor+1 trilinear corners, indices clipped into
// the padded volume. Clipped samples always land on the zero pad ring, so a
// bounds-checked sampler (0 outside padded-interior) + unclipped weights is
// exact.
//
// R5 -> R6: l1tex pipe is the wall (81%), displacement field is white noise
// so gather scatter is irreducible. Process 2 voxels per thread along d
// (overlapping gather rows -> L1 reuse within the thread, 2x MLP) and use
// __ldcs for the streaming displacement reads so they stop evicting gather
// lines from L1.

namespace {
constexpr int D = 160, H = 192, W = 224;
constexpr int HW  = H * W;          // 43008
constexpr int VOL = D * H * W;      // 6881280
}

// Sample one (d,h) row at padded w-index iw; rowok = (d,h) row in bounds.
__device__ __forceinline__ float samp_row(const float* __restrict__ row,
                                          bool rowok, int iw) {
    unsigned uw = (unsigned)(iw - 1);
    if (rowok && uw < (unsigned)W) {
        return __ldg(row + uw);
    }
    return 0.0f;
}

// Full trilinear sample for one voxel; arithmetic order matches reference.
__device__ __forceinline__ float voxel(const float* __restrict__ img,
                                       float ddv, float dhv, float dwv,
                                       int d, int h, int w) {
    float Dup = ddv + (float)d + 1.0f;
    float Hup = dhv + (float)h + 1.0f;
    float Wup = dwv + (float)w + 1.0f;

    float fd = floorf(Dup);
    float fh = floorf(Hup);
    float fw = floorf(Wup);
    int df = (int)fd, hf = (int)fh, wf = (int)fw;
    int dc = df + 1,  hc = hf + 1;

    float wd = (fd + 1.0f) - Dup;
    float wh = (fh + 1.0f) - Hup;
    float ww = (fw + 1.0f) - Wup;
    float wd1 = 1.0f - wd;
    float wh1 = 1.0f - wh;
    float ww1 = 1.0f - ww;

    bool dfo = (unsigned)(df - 1) < (unsigned)D;
    bool dco = (unsigned)(dc - 1) < (unsigned)D;
    bool hfo = (unsigned)(hf - 1) < (unsigned)H;
    bool hco = (unsigned)(hc - 1) < (unsigned)H;

    const float* row_ff = img + (ptrdiff_t)(df - 1) * HW + (ptrdiff_t)(hf - 1) * W;
    const float* row_fc = row_ff + W;    // hc = hf + 1
    const float* row_cf = row_ff + HW;   // dc = df + 1
    const float* row_cc = row_cf + W;

    int wc = wf + 1;
    float acc;
    acc  = samp_row(row_ff, dfo && hfo, wf) * (wd  * wh  * ww );
    acc += samp_row(row_ff, dfo && hfo, wc) * (wd  * wh  * ww1);
    acc += samp_row(row_fc, dfo && hco, wf) * (wd  * wh1 * ww );
    acc += samp_row(row_fc, dfo && hco, wc) * (wd  * wh1 * ww1);
    acc += samp_row(row_cf, dco && hfo, wf) * (wd1 * wh  * ww );
    acc += samp_row(row_cf, dco && hfo, wc) * (wd1 * wh  * ww1);
    acc += samp_row(row_cc, dco && hco, wf) * (wd1 * wh1 * ww );
    acc += samp_row(row_cc, dco && hco, wc) * (wd1 * wh1 * ww1);
    return acc;
}

__global__ void __launch_bounds__(256)
warp3d_kernel(const float* __restrict__ img,    // VOL floats
              const float* __restrict__ disp,   // 3*VOL floats (dD, dH, dW)
              float* __restrict__ out)          // VOL floats
{
    // Block covers a 32(w) x 8(h) tile of TWO adjacent d-slices.
    int w  = blockIdx.x * 32 + threadIdx.x;
    int h  = blockIdx.y * 8 + threadIdx.y;
    int d0 = blockIdx.z * 2;
    int n0 = d0 * HW + h * W + w;
    int n1 = n0 + HW;

    // Streaming displacement reads: evict-first so they don't pollute L1.
    float dd0 = __ldcs(disp + n0);
    float dh0 = __ldcs(disp + VOL + n0);
    float dw0 = __ldcs(disp + 2 * VOL + n0);
    float dd1 = __ldcs(disp + n1);
    float dh1 = __ldcs(disp + VOL + n1);
    float dw1 = __ldcs(disp + 2 * VOL + n1);

    float r0 = voxel(img, dd0, dh0, dw0, d0,     h, w);
    float r1 = voxel(img, dd1, dh1, dw1, d0 + 1, h, w);

    out[n0] = r0;
    out[n1] = r1;
}

extern "C" void kernel_launch(void* const* d_in, const int* in_sizes, int n_in,
                              void* d_out, int out_size) {
    const float* img  = (const float*)d_in[0];   // input1: VOL elements
    const float* disp = (const float*)d_in[1];   // input2: 3*VOL elements
    float* out = (float*)d_out;

    dim3 block(32, 8, 1);
    dim3 grid(W / 32, H / 8, D / 2);   // 7 x 24 x 80
    warp3d_kernel<<<grid, block>>>(img, disp, out);
}